// round 5
// baseline (speedup 1.0000x reference)
#include <cuda_runtime.h>

// out[B,18] = Theta(x)[B,1330] @ (big_xi * mask)[1330,18]
// x = concat(z[B,16], betas[B,2]); Theta = monomials deg 0..3 in
// combinations_with_replacement order == nested i<=j<=k loops.
//
// R=4 rows per thread: each broadcast W-row load (5 LDS) feeds 36 independent
// FFMA2 -> ILP hides LDS latency at 1 CTA/SM; grid=147 ~ one balanced wave.

#define BLOCK   224     // 7 warps
#define R_ROWS  4
#define CHUNK   (BLOCK * R_ROWS)   // 896 rows per block
#define NVARS   18
#define P_TOT   1330
#define WPAD    20      // padded W row stride (floats): 80B, 16B-aligned rows
#define NACC    9       // 18 outputs as 9 packed f32x2 accumulators

typedef unsigned long long u64;

__device__ __forceinline__ u64 pack2(float t) {
    u64 r;
    asm("mov.b64 %0, {%1, %1};" : "=l"(r) : "f"(t));
    return r;
}
__device__ __forceinline__ u64 ffma2(u64 a, u64 b, u64 c) {
    u64 r;
    asm("fma.rn.f32x2 %0, %1, %2, %3;" : "=l"(r) : "l"(a), "l"(b), "l"(c));
    return r;
}
__device__ __forceinline__ void unpack2(u64 v, float& x, float& y) {
    asm("mov.b64 {%0, %1}, %2;" : "=f"(x), "=f"(y) : "l"(v));
}

__global__ __launch_bounds__(BLOCK, 1)
void vindy_poly_kernel(const float* __restrict__ z,
                       const float* __restrict__ betas,
                       const float* __restrict__ big_xi,
                       const float* __restrict__ mask,
                       float* __restrict__ out,
                       int rows)
{
    extern __shared__ __align__(16) float smem[];
    float* Wsh = smem;                       // P_TOT * WPAD floats (padded rows)
    float* xsh = smem + P_TOT * WPAD;        // NVARS * CHUNK floats (transposed)

    const int tid  = threadIdx.x;
    const int base = blockIdx.x * CHUNK;

    // Stage W = big_xi * mask into shared (padded rows).
    for (int p = tid; p < P_TOT; p += BLOCK) {
        const float* gx = big_xi + p * NVARS;
        const float* gm = mask   + p * NVARS;
        float* wrow = Wsh + p * WPAD;
        #pragma unroll
        for (int n = 0; n < NVARS; ++n) wrow[n] = gx[n] * gm[n];
    }

    // Stage this block's x = [z | betas] transposed: xsh[v*CHUNK + r].
    #pragma unroll
    for (int rr = 0; rr < R_ROWS; ++rr) {
        const int rloc = tid + rr * BLOCK;
        int grow = base + rloc;
        if (grow > rows - 1) grow = rows - 1;     // clamp (extra results discarded)
        const float4* zr = (const float4*)(z + (size_t)grow * 16);
        float4 a = zr[0], b = zr[1], c = zr[2], d = zr[3];
        xsh[ 0 * CHUNK + rloc] = a.x;  xsh[ 1 * CHUNK + rloc] = a.y;
        xsh[ 2 * CHUNK + rloc] = a.z;  xsh[ 3 * CHUNK + rloc] = a.w;
        xsh[ 4 * CHUNK + rloc] = b.x;  xsh[ 5 * CHUNK + rloc] = b.y;
        xsh[ 6 * CHUNK + rloc] = b.z;  xsh[ 7 * CHUNK + rloc] = b.w;
        xsh[ 8 * CHUNK + rloc] = c.x;  xsh[ 9 * CHUNK + rloc] = c.y;
        xsh[10 * CHUNK + rloc] = c.z;  xsh[11 * CHUNK + rloc] = c.w;
        xsh[12 * CHUNK + rloc] = d.x;  xsh[13 * CHUNK + rloc] = d.y;
        xsh[14 * CHUNK + rloc] = d.z;  xsh[15 * CHUNK + rloc] = d.w;
        const float2 bb = *(const float2*)(betas + (size_t)grow * 2);
        xsh[16 * CHUNK + rloc] = bb.x; xsh[17 * CHUNK + rloc] = bb.y;
    }
    __syncthreads();

    u64 acc[R_ROWS][NACC];
    const float* w = Wsh;

    // Degree 0: constant column contributes W row 0 directly.
    {
        const ulonglong2* wv = (const ulonglong2*)w;
        ulonglong2 w01 = wv[0], w23 = wv[1], w45 = wv[2], w67 = wv[3];
        u64 w8 = *(const u64*)(w + 16);
        #pragma unroll
        for (int r = 0; r < R_ROWS; ++r) {
            acc[r][0] = w01.x; acc[r][1] = w01.y;
            acc[r][2] = w23.x; acc[r][3] = w23.y;
            acc[r][4] = w45.x; acc[r][5] = w45.y;
            acc[r][6] = w67.x; acc[r][7] = w67.y;
            acc[r][8] = w8;
        }
        w += WPAD;
    }

    // Per-row x column bases (stride CHUNK floats between variables).
    const float* xb[R_ROWS];
    #pragma unroll
    for (int r = 0; r < R_ROWS; ++r) xb[r] = xsh + tid + r * BLOCK;

    // Apply one W row to all R_ROWS accumulators given packed theta t[r].
    #define ACCR(T) do {                                                      \
        const ulonglong2* _wv = (const ulonglong2*)w;                         \
        ulonglong2 _w01 = _wv[0], _w23 = _wv[1], _w45 = _wv[2], _w67 = _wv[3];\
        u64 _w8 = *(const u64*)(w + 16);                                      \
        _Pragma("unroll")                                                     \
        for (int _r = 0; _r < R_ROWS; ++_r) {                                 \
            acc[_r][0] = ffma2((T)[_r], _w01.x, acc[_r][0]);                  \
            acc[_r][1] = ffma2((T)[_r], _w01.y, acc[_r][1]);                  \
            acc[_r][2] = ffma2((T)[_r], _w23.x, acc[_r][2]);                  \
            acc[_r][3] = ffma2((T)[_r], _w23.y, acc[_r][3]);                  \
            acc[_r][4] = ffma2((T)[_r], _w45.x, acc[_r][4]);                  \
            acc[_r][5] = ffma2((T)[_r], _w45.y, acc[_r][5]);                  \
            acc[_r][6] = ffma2((T)[_r], _w67.x, acc[_r][6]);                  \
            acc[_r][7] = ffma2((T)[_r], _w67.y, acc[_r][7]);                  \
            acc[_r][8] = ffma2((T)[_r], _w8,    acc[_r][8]);                  \
        }                                                                     \
        w += WPAD;                                                            \
    } while (0)

    // Degree 1
    #pragma unroll 1
    for (int i = 0; i < NVARS; ++i) {
        u64 t[R_ROWS];
        #pragma unroll
        for (int r = 0; r < R_ROWS; ++r) t[r] = pack2(xb[r][i * CHUNK]);
        ACCR(t);
    }

    // Degree 2
    #pragma unroll 1
    for (int i = 0; i < NVARS; ++i) {
        float xi[R_ROWS];
        #pragma unroll
        for (int r = 0; r < R_ROWS; ++r) xi[r] = xb[r][i * CHUNK];
        #pragma unroll 1
        for (int j = i; j < NVARS; ++j) {
            u64 t[R_ROWS];
            #pragma unroll
            for (int r = 0; r < R_ROWS; ++r) t[r] = pack2(xi[r] * xb[r][j * CHUNK]);
            ACCR(t);
        }
    }

    // Degree 3 (pij hoisted out of the k loop)
    #pragma unroll 1
    for (int i = 0; i < NVARS; ++i) {
        float xi[R_ROWS];
        #pragma unroll
        for (int r = 0; r < R_ROWS; ++r) xi[r] = xb[r][i * CHUNK];
        #pragma unroll 1
        for (int j = i; j < NVARS; ++j) {
            float pij[R_ROWS];
            #pragma unroll
            for (int r = 0; r < R_ROWS; ++r) pij[r] = xi[r] * xb[r][j * CHUNK];
            #pragma unroll 2
            for (int k = j; k < NVARS; ++k) {
                u64 t[R_ROWS];
                #pragma unroll
                for (int r = 0; r < R_ROWS; ++r) t[r] = pack2(pij[r] * xb[r][k * CHUNK]);
                ACCR(t);
            }
        }
    }

    // Write 18 outputs per row as 9 float2 stores (rows are 72B strided).
    #pragma unroll
    for (int rr = 0; rr < R_ROWS; ++rr) {
        const int grow = base + tid + rr * BLOCK;
        if (grow < rows) {
            float* o = out + (size_t)grow * NVARS;
            #pragma unroll
            for (int n = 0; n < NACC; ++n) {
                float a, b;
                unpack2(acc[rr][n], a, b);
                ((float2*)o)[n] = make_float2(a, b);
            }
        }
    }
    #undef ACCR
}

extern "C" void kernel_launch(void* const* d_in, const int* in_sizes, int n_in,
                              void* d_out, int out_size)
{
    const float* z      = (const float*)d_in[0];
    const float* betas  = (const float*)d_in[1];
    const float* big_xi = (const float*)d_in[2];
    const float* mask   = (const float*)d_in[3];
    float* out = (float*)d_out;

    const int rows = in_sizes[0] / 16;   // z is [rows, 16]
    const int smem_bytes = (P_TOT * WPAD + NVARS * CHUNK) * (int)sizeof(float);

    cudaFuncSetAttribute(vindy_poly_kernel,
                         cudaFuncAttributeMaxDynamicSharedMemorySize, smem_bytes);

    const int grid = (rows + CHUNK - 1) / CHUNK;
    vindy_poly_kernel<<<grid, BLOCK, smem_bytes>>>(z, betas, big_xi, mask, out, rows);
}

// round 8
// speedup vs baseline: 1.0571x; 1.0571x over previous
#include <cuda_runtime.h>
#include <cstdint>

// out[B,18] = Theta(x)[B,1330] @ (big_xi*mask)[1330,18]
// via classic mma.sync tf32 m16n8k8 (plain sm_80+ PTX -> works at sm_103 target).
// K padded to 1408 = 11 chunks x 128. Theta tile built per chunk in smem.

typedef unsigned int u32;
typedef unsigned long long u64;

#define NVARS    18
#define KPAD     1408
#define NCHUNK   11
#define KSTEPS   16          // k-steps (of 8) per chunk
#define NTILES   3           // N=24 as 3 x n8
#define MTILE    128
#define THREADS  256
#define TSTRIDE  132         // theta row stride in floats (conflict-free)

// ---- compile-time monomial table: p -> i | j<<8 | k<<16 (18 = const 1.0) ----
struct TabT { unsigned v[KPAD]; };
constexpr TabT make_tab() {
    TabT t{};
    int p = 0;
    t.v[p++] = 18u | (18u << 8) | (18u << 16);                       // deg 0
    for (int i = 0; i < 18; i++)                                     // deg 1
        t.v[p++] = (unsigned)i | (18u << 8) | (18u << 16);
    for (int i = 0; i < 18; i++)                                     // deg 2
        for (int j = i; j < 18; j++)
            t.v[p++] = (unsigned)i | ((unsigned)j << 8) | (18u << 16);
    for (int i = 0; i < 18; i++)                                     // deg 3
        for (int j = i; j < 18; j++)
            for (int k = j; k < 18; k++)
                t.v[p++] = (unsigned)i | ((unsigned)j << 8) | ((unsigned)k << 16);
    for (; p < KPAD; p++) t.v[p] = 18u | (18u << 8) | (18u << 16);   // padding
    return t;
}
__constant__ TabT g_tab = make_tab();

// Prepacked tf32 B fragments: [kstep 176][ntile 3][lane 32][2] floats
__device__ __align__(16) float g_Bfrag[176 * NTILES * 32 * 2];

__device__ __forceinline__ u32 tf32_bits(float f) {
    u32 u;
    asm("cvt.rna.tf32.f32 %0, %1;" : "=r"(u) : "f"(f));
    return u;
}

__device__ __forceinline__ void mma_tf32(float* d, u32 a0, u32 a1, u32 a2, u32 a3,
                                         u32 b0, u32 b1) {
    asm volatile(
        "mma.sync.aligned.m16n8k8.row.col.f32.tf32.tf32.f32 "
        "{%0,%1,%2,%3}, {%4,%5,%6,%7}, {%8,%9}, {%0,%1,%2,%3};"
        : "+f"(d[0]), "+f"(d[1]), "+f"(d[2]), "+f"(d[3])
        : "r"(a0), "r"(a1), "r"(a2), "r"(a3), "r"(b0), "r"(b1));
}

// ---------------- prep: pack W into per-lane tf32 B fragments ----------------
// B fragment (m16n8k8.row.col): b0 = B[k = 8s + (lane&3)][n = (lane>>2) + 8t],
//                               b1 = same with k+4.
__global__ void prep_bfrag(const float* __restrict__ xi, const float* __restrict__ mk) {
    int idx = blockIdx.x * blockDim.x + threadIdx.x;
    if (idx >= 176 * NTILES * 32 * 2) return;
    int e    = idx & 1;
    int lane = (idx >> 1) & 31;
    int st   = idx >> 6;           // s*3 + t
    int t    = st % 3;
    int s    = st / 3;
    int k = 8 * s + (lane & 3) + 4 * e;
    int n = (lane >> 2) + 8 * t;
    float v = 0.f;
    if (k < 1330 && n < NVARS) v = xi[k * NVARS + n] * mk[k * NVARS + n];
    g_Bfrag[idx] = __uint_as_float(tf32_bits(v));
}

// ---------------- main kernel ------------------------------------------------
// smem: theta[128][132] u32 | bfrag chunk [16][3][32][2] f32 | x[19][128] | tab[1408]
#define OFF_TH   0
#define OFF_BF   (OFF_TH + MTILE * TSTRIDE * 4)          // 67584
#define OFF_X    (OFF_BF + KSTEPS * NTILES * 64 * 4)     // +12288
#define OFF_TAB  (OFF_X + 19 * 128 * 4)                  // +9728
#define SMEM_TOT (OFF_TAB + KPAD * 4)                    // +5632 = 95232 B

__global__ __launch_bounds__(THREADS, 2)
void vindy_mma_kernel(const float* __restrict__ z,
                      const float* __restrict__ betas,
                      float* __restrict__ out,
                      int rows)
{
    extern __shared__ __align__(16) char smem[];
    u32*   theta = (u32*)(smem + OFF_TH);
    float* bfr   = (float*)(smem + OFF_BF);
    float* xsh   = (float*)(smem + OFF_X);
    u32*   tab   = (u32*)(smem + OFF_TAB);

    const int tid  = threadIdx.x;
    const int wid  = tid >> 5;
    const int lane = tid & 31;
    const int row  = tid & 127;
    const int seg  = tid >> 7;          // 0/1: which 64 k-cols this thread builds

    // stage table
    for (int i = tid; i < KPAD; i += THREADS) tab[i] = g_tab.v[i];

    // stage x (transposed): xsh[v*128 + row], x[18] = 1
    if (tid < 128) {
        int grow = blockIdx.x * MTILE + tid;
        if (grow > rows - 1) grow = rows - 1;
        const float4* zr = (const float4*)(z + (size_t)grow * 16);
        float4 a = zr[0], b = zr[1], c = zr[2], d = zr[3];
        xsh[ 0*128 + tid] = a.x; xsh[ 1*128 + tid] = a.y;
        xsh[ 2*128 + tid] = a.z; xsh[ 3*128 + tid] = a.w;
        xsh[ 4*128 + tid] = b.x; xsh[ 5*128 + tid] = b.y;
        xsh[ 6*128 + tid] = b.z; xsh[ 7*128 + tid] = b.w;
        xsh[ 8*128 + tid] = c.x; xsh[ 9*128 + tid] = c.y;
        xsh[10*128 + tid] = c.z; xsh[11*128 + tid] = c.w;
        xsh[12*128 + tid] = d.x; xsh[13*128 + tid] = d.y;
        xsh[14*128 + tid] = d.z; xsh[15*128 + tid] = d.w;
        const float2 bb = *(const float2*)(betas + (size_t)grow * 2);
        xsh[16*128 + tid] = bb.x; xsh[17*128 + tid] = bb.y;
        xsh[18*128 + tid] = 1.0f;
    }
    __syncthreads();

    float d0[4] = {0,0,0,0}, d1[4] = {0,0,0,0}, d2[4] = {0,0,0,0};
    const float* xr = xsh + row;
    const int g  = lane >> 2;       // fragment row group 0..7
    const int cc = lane & 3;        // fragment k sub-col 0..3

    for (int c = 0; c < NCHUNK; ++c) {
        // ---- stage this chunk's B fragments (3072 floats = 768 float4) ----
        {
            const float4* src = (const float4*)g_Bfrag + c * (KSTEPS * NTILES * 16);
            float4* dst = (float4*)bfr;
            #pragma unroll
            for (int i = 0; i < 3; ++i) dst[tid + i * THREADS] = src[tid + i * THREADS];
        }

        // ---- build theta tile [128 rows][128 k] into [row][TSTRIDE] ----
        {
            const int p0 = seg * 64;
            u32* trow = theta + row * TSTRIDE;
            #pragma unroll 4
            for (int p4 = p0; p4 < p0 + 64; p4 += 4) {
                const uint4 e4 = *(const uint4*)&tab[c * 128 + p4];
                float t0 = xr[(e4.x & 255) * 128] * xr[((e4.x >> 8) & 255) * 128]
                         * xr[((e4.x >> 16) & 255) * 128];
                float t1 = xr[(e4.y & 255) * 128] * xr[((e4.y >> 8) & 255) * 128]
                         * xr[((e4.y >> 16) & 255) * 128];
                float t2 = xr[(e4.z & 255) * 128] * xr[((e4.z >> 8) & 255) * 128]
                         * xr[((e4.z >> 16) & 255) * 128];
                float t3 = xr[(e4.w & 255) * 128] * xr[((e4.w >> 8) & 255) * 128]
                         * xr[((e4.w >> 16) & 255) * 128];
                uint4 v = make_uint4(tf32_bits(t0), tf32_bits(t1),
                                     tf32_bits(t2), tf32_bits(t3));
                *(uint4*)(trow + p4) = v;
            }
        }
        __syncthreads();

        // ---- mma: warp owns rows [16*wid, 16*wid+16), 16 k-steps x 3 n-tiles --
        {
            const u32* Ar0 = theta + (16 * wid + g) * TSTRIDE;
            const u32* Ar1 = Ar0 + 8 * TSTRIDE;
            #pragma unroll
            for (int s = 0; s < KSTEPS; ++s) {
                const int ks = s * 8 + cc;
                u32 a0 = Ar0[ks], a1 = Ar1[ks], a2 = Ar0[ks + 4], a3 = Ar1[ks + 4];
                const uint2* bp = (const uint2*)bfr + (s * NTILES) * 32 + lane;
                uint2 b0 = bp[0], b1 = bp[32], b2 = bp[64];
                mma_tf32(d0, a0, a1, a2, a3, b0.x, b0.y);
                mma_tf32(d1, a0, a1, a2, a3, b1.x, b1.y);
                mma_tf32(d2, a0, a1, a2, a3, b2.x, b2.y);
            }
        }
        __syncthreads();
    }

    // ---- epilogue: D fragment c0=(r,2cc) c1=(r,2cc+1) c2=(r+8,2cc) c3=(r+8,2cc+1)
    {
        const int r0 = blockIdx.x * MTILE + 16 * wid + g;
        const int r1 = r0 + 8;
        // tile 0: cols 2cc, 2cc+1 ; tile 1: +8 ; tile 2: +16 (only cc==0 valid)
        if (r0 < rows) {
            float* o = out + (size_t)r0 * NVARS;
            *(float2*)(o + 2 * cc)     = make_float2(d0[0], d0[1]);
            *(float2*)(o + 2 * cc + 8) = make_float2(d1[0], d1[1]);
            if (cc == 0) *(float2*)(o + 16) = make_float2(d2[0], d2[1]);
        }
        if (r1 < rows) {
            float* o = out + (size_t)r1 * NVARS;
            *(float2*)(o + 2 * cc)     = make_float2(d0[2], d0[3]);
            *(float2*)(o + 2 * cc + 8) = make_float2(d1[2], d1[3]);
            if (cc == 0) *(float2*)(o + 16) = make_float2(d2[2], d2[3]);
        }
    }
}

extern "C" void kernel_launch(void* const* d_in, const int* in_sizes, int n_in,
                              void* d_out, int out_size)
{
    const float* z      = (const float*)d_in[0];
    const float* betas  = (const float*)d_in[1];
    const float* big_xi = (const float*)d_in[2];
    const float* mask   = (const float*)d_in[3];
    float* out = (float*)d_out;

    const int rows = in_sizes[0] / 16;   // z is [rows, 16]

    prep_bfrag<<<(176 * NTILES * 64 + 255) / 256, 256>>>(big_xi, mask);

    cudaFuncSetAttribute(vindy_mma_kernel,
                         cudaFuncAttributeMaxDynamicSharedMemorySize, SMEM_TOT);
    const int grid = (rows + MTILE - 1) / MTILE;
    vindy_mma_kernel<<<grid, THREADS, SMEM_TOT>>>(z, betas, out, rows);
}

// round 12
// speedup vs baseline: 1.9577x; 1.8520x over previous
#include <cuda_runtime.h>
#include <cstdint>
#include <utility>

// out[B,18] = Theta(x)[B,1330] @ (big_xi*mask)[1330,18]
// mma.sync tf32 m16n8k8. K padded to 1408 = 11 chunks x 128.
// Theta built from REGISTER x with fully unrolled compile-time monomial
// indices -> zero LDS in the build; smem traffic ~halved vs round 8.

typedef unsigned int u32;

#define NVARS    18
#define KPAD     1408
#define NCHUNK   11
#define KSTEPS   16          // k-steps (of 8) per chunk
#define NTILES   3           // N=24 as 3 x n8
#define MTILE    128
#define THREADS  256
#define TSTRIDE  132         // theta row stride (floats): STS.128/LDS.32 conflict-free

// ---- compile-time monomial triple for index p: i | j<<5 | k<<10 (18 = one) --
__host__ __device__ constexpr u32 tab_at(int p) {
    if (p == 0) return 18u | (18u << 5) | (18u << 10);
    int q = 1;
    for (int i = 0; i < 18; i++)
        if (q++ == p) return (u32)i | (18u << 5) | (18u << 10);
    for (int i = 0; i < 18; i++)
        for (int j = i; j < 18; j++)
            if (q++ == p) return (u32)i | ((u32)j << 5) | (18u << 10);
    for (int i = 0; i < 18; i++)
        for (int j = i; j < 18; j++)
            for (int k = j; k < 18; k++)
                if (q++ == p) return (u32)i | ((u32)j << 5) | ((u32)k << 10);
    return 18u | (18u << 5) | (18u << 10);   // padding
}

// Prepacked tf32 B fragments: [kstep 176][ntile 3][lane 32][2] floats
__device__ __align__(16) float g_Bfrag[176 * NTILES * 32 * 2];

__device__ __forceinline__ u32 tf32_bits(float f) {
    u32 u;
    asm("cvt.rna.tf32.f32 %0, %1;" : "=r"(u) : "f"(f));
    return u;
}

__device__ __forceinline__ void mma_tf32(float* d, u32 a0, u32 a1, u32 a2, u32 a3,
                                         u32 b0, u32 b1) {
    asm volatile(
        "mma.sync.aligned.m16n8k8.row.col.f32.tf32.tf32.f32 "
        "{%0,%1,%2,%3}, {%4,%5,%6,%7}, {%8,%9}, {%0,%1,%2,%3};"
        : "+f"(d[0]), "+f"(d[1]), "+f"(d[2]), "+f"(d[3])
        : "r"(a0), "r"(a1), "r"(a2), "r"(a3), "r"(b0), "r"(b1));
}

// ---------------- prep: pack W into per-lane tf32 B fragments ----------------
// m16n8k8.row.col B frag: b0 = B[k = 8s + (lane&3)][n = (lane>>2) + 8t], b1: k+4.
__global__ void prep_bfrag(const float* __restrict__ xi, const float* __restrict__ mk) {
    int idx = blockIdx.x * blockDim.x + threadIdx.x;
    if (idx >= 176 * NTILES * 32 * 2) return;
    int e    = idx & 1;
    int lane = (idx >> 1) & 31;
    int st   = idx >> 6;           // s*3 + t
    int t    = st % 3;
    int s    = st / 3;
    int k = 8 * s + (lane & 3) + 4 * e;
    int n = (lane >> 2) + 8 * t;
    float v = 0.f;
    if (k < 1330 && n < NVARS) v = xi[k * NVARS + n] * mk[k * NVARS + n];
    g_Bfrag[idx] = __uint_as_float(tf32_bits(v));
}

// ---------------- compile-time theta build ----------------------------------
template<int SEG, int P>
__device__ __forceinline__ void mono_step(u32* __restrict__ trow,
                                          const float (&x)[19],
                                          u32 (&v)[4]) {
    if constexpr (((P >> 6) & 1) == SEG) {
        float t;
        if constexpr (P >= 1330) {
            t = 0.0f;
        } else if constexpr (P == 0) {
            t = 1.0f;
        } else {
            constexpr u32 e = tab_at(P);
            constexpr int i = e & 31, j = (e >> 5) & 31, k = (e >> 10) & 31;
            if constexpr (j == 18)       t = x[i];
            else if constexpr (k == 18)  t = x[i] * x[j];
            else                         t = (x[i] * x[j]) * x[k];
        }
        v[P & 3] = tf32_bits(t);
        if constexpr ((P & 3) == 3) {
            *(uint4*)(trow + (P & 127) - 3) = make_uint4(v[0], v[1], v[2], v[3]);
        }
    }
}

template<int SEG, int C, size_t... PP>
__device__ __forceinline__ void build_chunk(u32* __restrict__ trow,
                                            const float (&x)[19],
                                            std::index_sequence<PP...>) {
    u32 v[4];
    (mono_step<SEG, C * 128 + (int)PP>(trow, x, v), ...);
}

// ---------------- per-chunk body ---------------------------------------------
// smem layout
#define OFF_TH   0
#define OFF_BF   (OFF_TH + MTILE * TSTRIDE * 4)          // 67584
#define SMEM_TOT (OFF_BF + KSTEPS * NTILES * 64 * 4)     // +12288 = 79872 B

template<int C>
__device__ __forceinline__ void do_chunk(char* smem, const float (&x)[19],
                                         int tid, int wid, int lane, int seg,
                                         float (&d0)[4], float (&d1)[4], float (&d2)[4]) {
    u32*   theta = (u32*)(smem + OFF_TH);
    float* bfr   = (float*)(smem + OFF_BF);
    const int row = tid & 127;
    const int g   = lane >> 2;
    const int cc  = lane & 3;

    // prefetch this chunk's B fragments (3072 floats = 768 float4; 3/thread)
    float4 bf0, bf1, bf2;
    {
        const float4* src = (const float4*)g_Bfrag + C * (KSTEPS * NTILES * 16);
        bf0 = src[tid]; bf1 = src[tid + THREADS]; bf2 = src[tid + 2 * THREADS];
    }

    // build this thread's 64-slot half of the theta tile (registers -> STS.128)
    {
        u32* trow = theta + row * TSTRIDE;
        if (seg == 0) build_chunk<0, C>(trow, x, std::make_index_sequence<128>{});
        else          build_chunk<1, C>(trow, x, std::make_index_sequence<128>{});
    }

    // stage B
    {
        float4* dst = (float4*)bfr;
        dst[tid] = bf0; dst[tid + THREADS] = bf1; dst[tid + 2 * THREADS] = bf2;
    }
    __syncthreads();

    // mma: warp owns rows [16*wid, 16*wid+16), 16 k-steps x 3 n-tiles
    {
        const u32* Ar0 = theta + (16 * wid + g) * TSTRIDE;
        const u32* Ar1 = Ar0 + 8 * TSTRIDE;
        #pragma unroll
        for (int s = 0; s < KSTEPS; ++s) {
            const int ks = s * 8 + cc;
            u32 a0 = Ar0[ks], a1 = Ar1[ks], a2 = Ar0[ks + 4], a3 = Ar1[ks + 4];
            const uint2* bp = (const uint2*)bfr + (s * NTILES) * 32 + lane;
            uint2 b0 = bp[0], b1 = bp[32], b2 = bp[64];
            mma_tf32(d0, a0, a1, a2, a3, b0.x, b0.y);
            mma_tf32(d1, a0, a1, a2, a3, b1.x, b1.y);
            mma_tf32(d2, a0, a1, a2, a3, b2.x, b2.y);
        }
    }
    __syncthreads();
}

template<size_t... CC>
__device__ __forceinline__ void do_all(char* smem, const float (&x)[19],
                                       int tid, int wid, int lane, int seg,
                                       float (&d0)[4], float (&d1)[4], float (&d2)[4],
                                       std::index_sequence<CC...>) {
    (do_chunk<(int)CC>(smem, x, tid, wid, lane, seg, d0, d1, d2), ...);
}

// ---------------- main kernel ------------------------------------------------
__global__ __launch_bounds__(THREADS, 2)
void vindy_mma_kernel(const float* __restrict__ z,
                      const float* __restrict__ betas,
                      float* __restrict__ out,
                      int rows)
{
    extern __shared__ __align__(16) char smem[];
    const int tid  = threadIdx.x;
    const int wid  = tid >> 5;
    const int lane = tid & 31;
    const int seg  = tid >> 7;

    // load this thread's row x into registers (both segs load the same row)
    float x[19];
    {
        int grow = blockIdx.x * MTILE + (tid & 127);
        if (grow > rows - 1) grow = rows - 1;
        const float4* zr = (const float4*)(z + (size_t)grow * 16);
        float4 a = zr[0], b = zr[1], c = zr[2], d = zr[3];
        x[0] = a.x;  x[1] = a.y;  x[2]  = a.z;  x[3]  = a.w;
        x[4] = b.x;  x[5] = b.y;  x[6]  = b.z;  x[7]  = b.w;
        x[8] = c.x;  x[9] = c.y;  x[10] = c.z;  x[11] = c.w;
        x[12] = d.x; x[13] = d.y; x[14] = d.z;  x[15] = d.w;
        const float2 bb = *(const float2*)(betas + (size_t)grow * 2);
        x[16] = bb.x; x[17] = bb.y; x[18] = 1.0f;
    }

    float d0[4] = {0,0,0,0}, d1[4] = {0,0,0,0}, d2[4] = {0,0,0,0};

    do_all(smem, x, tid, wid, lane, seg, d0, d1, d2,
           std::make_index_sequence<NCHUNK>{});

    // epilogue: D frag c0=(r,2cc) c1=(r,2cc+1) c2=(r+8,2cc) c3=(r+8,2cc+1)
    {
        const int g  = lane >> 2;
        const int cc = lane & 3;
        const int r0 = blockIdx.x * MTILE + 16 * wid + g;
        const int r1 = r0 + 8;
        if (r0 < rows) {
            float* o = out + (size_t)r0 * NVARS;
            *(float2*)(o + 2 * cc)     = make_float2(d0[0], d0[1]);
            *(float2*)(o + 2 * cc + 8) = make_float2(d1[0], d1[1]);
            if (cc == 0) *(float2*)(o + 16) = make_float2(d2[0], d2[1]);
        }
        if (r1 < rows) {
            float* o = out + (size_t)r1 * NVARS;
            *(float2*)(o + 2 * cc)     = make_float2(d0[2], d0[3]);
            *(float2*)(o + 2 * cc + 8) = make_float2(d1[2], d1[3]);
            if (cc == 0) *(float2*)(o + 16) = make_float2(d2[2], d2[3]);
        }
    }
}

extern "C" void kernel_launch(void* const* d_in, const int* in_sizes, int n_in,
                              void* d_out, int out_size)
{
    const float* z      = (const float*)d_in[0];
    const float* betas  = (const float*)d_in[1];
    const float* big_xi = (const float*)d_in[2];
    const float* mask   = (const float*)d_in[3];
    float* out = (float*)d_out;

    const int rows = in_sizes[0] / 16;   // z is [rows, 16]

    prep_bfrag<<<(176 * NTILES * 64 + 255) / 256, 256>>>(big_xi, mask);

    cudaFuncSetAttribute(vindy_mma_kernel,
                         cudaFuncAttributeMaxDynamicSharedMemorySize, SMEM_TOT);
    const int grid = (rows + MTILE - 1) / MTILE;
    vindy_mma_kernel<<<grid, THREADS, SMEM_TOT>>>(z, betas, out, rows);
}

// round 13
// speedup vs baseline: 2.2278x; 1.1380x over previous
#include <cuda_runtime.h>
#include <cstdint>
#include <utility>

// out[B,18] = Theta(x)[B,1330] @ (big_xi*mask)[1330,18]
// mma.sync tf32 m16n8k8. K padded to 1408 = 11 chunks x 128.
// Theta built from REGISTER x, compile-time-unrolled monomials (no LDS in build).
// Warp layout: 4 m-groups (2 m-tiles = 32 rows) x 2 K-halves (8 k-steps each)
// -> B fragment LDS traffic halved vs 1-m-tile-per-warp; cross-K reduction in smem.

typedef unsigned int u32;

#define NVARS    18
#define KPAD     1408
#define NCHUNK   11
#define KSTEPS   16          // k-steps (of 8) per chunk
#define NTILES   3           // N=24 as 3 x n8
#define MTILE    128
#define THREADS  256
#define TSTRIDE  132         // theta row stride (floats): STS.128/LDS.32 conflict-free
#define RSTRIDE  25          // reduction buffer per-row stride (floats), conflict-free

// ---- compile-time monomial triple for index p: i | j<<5 | k<<10 (18 = one) --
__host__ __device__ constexpr u32 tab_at(int p) {
    if (p == 0) return 18u | (18u << 5) | (18u << 10);
    int q = 1;
    for (int i = 0; i < 18; i++)
        if (q++ == p) return (u32)i | (18u << 5) | (18u << 10);
    for (int i = 0; i < 18; i++)
        for (int j = i; j < 18; j++)
            if (q++ == p) return (u32)i | ((u32)j << 5) | (18u << 10);
    for (int i = 0; i < 18; i++)
        for (int j = i; j < 18; j++)
            for (int k = j; k < 18; k++)
                if (q++ == p) return (u32)i | ((u32)j << 5) | ((u32)k << 10);
    return 18u | (18u << 5) | (18u << 10);   // padding
}

// Prepacked tf32 B fragments: [kstep 176][ntile 3][lane 32][2] floats
__device__ __align__(16) float g_Bfrag[176 * NTILES * 32 * 2];

__device__ __forceinline__ u32 tf32_bits(float f) {
    u32 u;
    asm("cvt.rna.tf32.f32 %0, %1;" : "=r"(u) : "f"(f));
    return u;
}

__device__ __forceinline__ void mma_tf32(float* d, u32 a0, u32 a1, u32 a2, u32 a3,
                                         u32 b0, u32 b1) {
    asm volatile(
        "mma.sync.aligned.m16n8k8.row.col.f32.tf32.tf32.f32 "
        "{%0,%1,%2,%3}, {%4,%5,%6,%7}, {%8,%9}, {%0,%1,%2,%3};"
        : "+f"(d[0]), "+f"(d[1]), "+f"(d[2]), "+f"(d[3])
        : "r"(a0), "r"(a1), "r"(a2), "r"(a3), "r"(b0), "r"(b1));
}

// ---------------- prep: pack W into per-lane tf32 B fragments ----------------
// m16n8k8.row.col B frag: b0 = B[k = 8s + (lane&3)][n = (lane>>2) + 8t], b1: k+4.
__global__ void prep_bfrag(const float* __restrict__ xi, const float* __restrict__ mk) {
    int idx = blockIdx.x * blockDim.x + threadIdx.x;
    if (idx >= 176 * NTILES * 32 * 2) return;
    int e    = idx & 1;
    int lane = (idx >> 1) & 31;
    int st   = idx >> 6;           // s*3 + t
    int t    = st % 3;
    int s    = st / 3;
    int k = 8 * s + (lane & 3) + 4 * e;
    int n = (lane >> 2) + 8 * t;
    float v = 0.f;
    if (k < 1330 && n < NVARS) v = xi[k * NVARS + n] * mk[k * NVARS + n];
    g_Bfrag[idx] = __uint_as_float(tf32_bits(v));
}

// ---------------- compile-time theta build ----------------------------------
template<int SEG, int P>
__device__ __forceinline__ void mono_step(u32* __restrict__ trow,
                                          const float (&x)[19],
                                          u32 (&v)[4]) {
    if constexpr (((P >> 6) & 1) == SEG) {
        float t;
        if constexpr (P >= 1330) {
            t = 0.0f;
        } else if constexpr (P == 0) {
            t = 1.0f;
        } else {
            constexpr u32 e = tab_at(P);
            constexpr int i = e & 31, j = (e >> 5) & 31, k = (e >> 10) & 31;
            if constexpr (j == 18)       t = x[i];
            else if constexpr (k == 18)  t = x[i] * x[j];
            else                         t = (x[i] * x[j]) * x[k];
        }
        v[P & 3] = tf32_bits(t);
        if constexpr ((P & 3) == 3) {
            *(uint4*)(trow + (P & 127) - 3) = make_uint4(v[0], v[1], v[2], v[3]);
        }
    }
}

template<int SEG, int C, size_t... PP>
__device__ __forceinline__ void build_chunk(u32* __restrict__ trow,
                                            const float (&x)[19],
                                            std::index_sequence<PP...>) {
    u32 v[4];
    (mono_step<SEG, C * 128 + (int)PP>(trow, x, v), ...);
}

// ---------------- per-chunk body ---------------------------------------------
// smem layout
#define OFF_TH   0
#define OFF_BF   (OFF_TH + MTILE * TSTRIDE * 4)          // 67584
#define SMEM_TOT (OFF_BF + KSTEPS * NTILES * 64 * 4)     // +12288 = 79872 B
// reduction buffer overlays theta area after the last chunk: 128*RSTRIDE*4 = 12.8KB

template<int C>
__device__ __forceinline__ void do_chunk(char* smem, const float (&x)[19],
                                         int tid, int lane, int mw, int kh, int seg,
                                         float (&d)[2][NTILES][4]) {
    u32*   theta = (u32*)(smem + OFF_TH);
    float* bfr   = (float*)(smem + OFF_BF);
    const int row = tid & 127;
    const int g   = lane >> 2;
    const int cc  = lane & 3;

    // prefetch this chunk's B fragments (3072 floats = 768 float4; 3/thread)
    float4 bf0, bf1, bf2;
    {
        const float4* src = (const float4*)g_Bfrag + C * (KSTEPS * NTILES * 16);
        bf0 = src[tid]; bf1 = src[tid + THREADS]; bf2 = src[tid + 2 * THREADS];
    }

    // build this thread's 64-slot half of the theta tile (registers -> STS.128)
    {
        u32* trow = theta + row * TSTRIDE;
        if (seg == 0) build_chunk<0, C>(trow, x, std::make_index_sequence<128>{});
        else          build_chunk<1, C>(trow, x, std::make_index_sequence<128>{});
    }

    // stage B
    {
        float4* dst = (float4*)bfr;
        dst[tid] = bf0; dst[tid + THREADS] = bf1; dst[tid + 2 * THREADS] = bf2;
    }
    __syncthreads();

    // mma: warp owns rows [32*mw, 32*mw+32) (2 m-tiles), k-steps [8*kh, 8*kh+8)
    {
        const u32* A0 = theta + (32 * mw + g) * TSTRIDE;   // tile0 row g
        #pragma unroll
        for (int s = 0; s < 8; ++s) {
            const int st = 8 * kh + s;
            const int ks = st * 8 + cc;
            u32 a00 = A0[ks],                a01 = A0[8 * TSTRIDE + ks];
            u32 a02 = A0[ks + 4],            a03 = A0[8 * TSTRIDE + ks + 4];
            u32 a10 = A0[16 * TSTRIDE + ks], a11 = A0[24 * TSTRIDE + ks];
            u32 a12 = A0[16 * TSTRIDE + ks + 4], a13 = A0[24 * TSTRIDE + ks + 4];
            const uint2* bp = (const uint2*)bfr + (st * NTILES) * 32 + lane;
            uint2 b0 = bp[0], b1 = bp[32], b2 = bp[64];
            mma_tf32(d[0][0], a00, a01, a02, a03, b0.x, b0.y);
            mma_tf32(d[0][1], a00, a01, a02, a03, b1.x, b1.y);
            mma_tf32(d[0][2], a00, a01, a02, a03, b2.x, b2.y);
            mma_tf32(d[1][0], a10, a11, a12, a13, b0.x, b0.y);
            mma_tf32(d[1][1], a10, a11, a12, a13, b1.x, b1.y);
            mma_tf32(d[1][2], a10, a11, a12, a13, b2.x, b2.y);
        }
    }
    __syncthreads();
}

template<size_t... CC>
__device__ __forceinline__ void do_all(char* smem, const float (&x)[19],
                                       int tid, int lane, int mw, int kh, int seg,
                                       float (&d)[2][NTILES][4],
                                       std::index_sequence<CC...>) {
    (do_chunk<(int)CC>(smem, x, tid, lane, mw, kh, seg, d), ...);
}

// ---------------- main kernel ------------------------------------------------
__global__ __launch_bounds__(THREADS, 2)
void vindy_mma_kernel(const float* __restrict__ z,
                      const float* __restrict__ betas,
                      float* __restrict__ out,
                      int rows)
{
    extern __shared__ __align__(16) char smem[];
    const int tid  = threadIdx.x;
    const int wid  = tid >> 5;
    const int lane = tid & 31;
    const int seg  = tid >> 7;
    const int mw   = wid & 3;        // m-group: rows [32*mw, 32*mw+32)
    const int kh   = wid >> 2;       // k-half: steps [8*kh, 8*kh+8)

    // load this thread's row x into registers (both segs load the same row)
    float x[19];
    {
        int grow = blockIdx.x * MTILE + (tid & 127);
        if (grow > rows - 1) grow = rows - 1;
        const float4* zr = (const float4*)(z + (size_t)grow * 16);
        float4 a = zr[0], b = zr[1], c = zr[2], d = zr[3];
        x[0] = a.x;  x[1] = a.y;  x[2]  = a.z;  x[3]  = a.w;
        x[4] = b.x;  x[5] = b.y;  x[6]  = b.z;  x[7]  = b.w;
        x[8] = c.x;  x[9] = c.y;  x[10] = c.z;  x[11] = c.w;
        x[12] = d.x; x[13] = d.y; x[14] = d.z;  x[15] = d.w;
        const float2 bb = *(const float2*)(betas + (size_t)grow * 2);
        x[16] = bb.x; x[17] = bb.y; x[18] = 1.0f;
    }

    float d[2][NTILES][4] = {};

    do_all(smem, x, tid, lane, mw, kh, seg, d,
           std::make_index_sequence<NCHUNK>{});

    // ---- cross-K reduction: kh=1 warps dump partials, kh=0 warps add ----
    {
        float* red = (float*)(smem + OFF_TH);   // reuse theta area (post-sync)
        if (kh == 1) {
            float* r = red + (mw * 32 + lane) * RSTRIDE;
            #pragma unroll
            for (int mt = 0; mt < 2; ++mt)
                #pragma unroll
                for (int t = 0; t < NTILES; ++t)
                    #pragma unroll
                    for (int e = 0; e < 4; ++e)
                        r[(mt * NTILES + t) * 4 + e] = d[mt][t][e];
        }
        __syncthreads();
        if (kh == 0) {
            const float* r = red + (mw * 32 + lane) * RSTRIDE;
            #pragma unroll
            for (int mt = 0; mt < 2; ++mt)
                #pragma unroll
                for (int t = 0; t < NTILES; ++t)
                    #pragma unroll
                    for (int e = 0; e < 4; ++e)
                        d[mt][t][e] += r[(mt * NTILES + t) * 4 + e];
        }
    }

    // ---- epilogue (kh=0 warps): frag c0=(r,2cc) c1=(r,2cc+1) c2/c3 = +8 row --
    if (kh == 0) {
        const int g  = lane >> 2;
        const int cc = lane & 3;
        #pragma unroll
        for (int mt = 0; mt < 2; ++mt) {
            const int r0 = blockIdx.x * MTILE + 32 * mw + 16 * mt + g;
            const int r1 = r0 + 8;
            if (r0 < rows) {
                float* o = out + (size_t)r0 * NVARS;
                *(float2*)(o + 2 * cc)     = make_float2(d[mt][0][0], d[mt][0][1]);
                *(float2*)(o + 2 * cc + 8) = make_float2(d[mt][1][0], d[mt][1][1]);
                if (cc == 0) *(float2*)(o + 16) = make_float2(d[mt][2][0], d[mt][2][1]);
            }
            if (r1 < rows) {
                float* o = out + (size_t)r1 * NVARS;
                *(float2*)(o + 2 * cc)     = make_float2(d[mt][0][2], d[mt][0][3]);
                *(float2*)(o + 2 * cc + 8) = make_float2(d[mt][1][2], d[mt][1][3]);
                if (cc == 0) *(float2*)(o + 16) = make_float2(d[mt][2][2], d[mt][2][3]);
            }
        }
    }
}

extern "C" void kernel_launch(void* const* d_in, const int* in_sizes, int n_in,
                              void* d_out, int out_size)
{
    const float* z      = (const float*)d_in[0];
    const float* betas  = (const float*)d_in[1];
    const float* big_xi = (const float*)d_in[2];
    const float* mask   = (const float*)d_in[3];
    float* out = (float*)d_out;

    const int rows = in_sizes[0] / 16;   // z is [rows, 16]

    prep_bfrag<<<(176 * NTILES * 64 + 255) / 256, 256>>>(big_xi, mask);

    cudaFuncSetAttribute(vindy_mma_kernel,
                         cudaFuncAttributeMaxDynamicSharedMemorySize, SMEM_TOT);
    const int grid = (rows + MTILE - 1) / MTILE;
    vindy_mma_kernel<<<grid, THREADS, SMEM_TOT>>>(z, betas, out, rows);
}